// round 16
// baseline (speedup 1.0000x reference)
#include <cuda_runtime.h>
#include <cuda_fp16.h>
#include <cstdint>

#define N_NODES 100000
#define N_EDGES 1600000
#define D 128
#define N_LAYERS 4
#define ROWU32 128          // 256 fp16 per activation row = 128 uint32 (agg|x)

// ---------------- scratch (__device__ globals; no allocation) ----------------
__device__ float g_invdeg[N_NODES];
__device__ int   g_deg[N_NODES];
__device__ int   g_cursor[N_NODES];
__device__ int   g_rowstart[N_NODES + 1];
__device__ int   g_csr_src[N_EDGES];
// Packed fp16 activations [row][k2]: k2<64 = agg-half (gather), >=64 = x-half
__device__ uint32_t g_A[(size_t)N_NODES * ROWU32];
// Packed fp16 weights [l][j][k2] combined (k<128 -> Wl, k>=128 -> Wr)
__device__ uint32_t g_Wh[N_LAYERS * D * ROWU32];

// ------------------------------ helpers -------------------------------------
__device__ __forceinline__ uint32_t smem_u32(const void* p) {
    uint32_t a;
    asm("{ .reg .u64 t; cvta.to.shared.u64 t, %1; cvt.u32.u64 %0, t; }"
        : "=r"(a) : "l"(p));
    return a;
}
__device__ __forceinline__ void cp16(uint32_t saddr, const void* g) {
    asm volatile("cp.async.ca.shared.global [%0], [%1], 16;"
                 :: "r"(saddr), "l"(g) : "memory");
}
#define CP_COMMIT() asm volatile("cp.async.commit_group;" ::: "memory")
#define CP_WAIT(n)  asm volatile("cp.async.wait_group %0;" :: "n"(n) : "memory")

__device__ __forceinline__ uint32_t pack_h2(__half a, __half b) {
    return ((uint32_t)__half_as_ushort(b) << 16) | (uint32_t)__half_as_ushort(a);
}
__device__ __forceinline__ float2 unpack_h2(uint32_t v) {
    __half2 h = *reinterpret_cast<__half2*>(&v);
    return __half22float2(h);
}

__device__ __forceinline__ void mma_fp16(float c[4], const uint32_t a[4],
                                         uint32_t b0, uint32_t b1) {
    asm volatile(
        "mma.sync.aligned.m16n8k16.row.col.f32.f16.f16.f32 "
        "{%0,%1,%2,%3}, {%4,%5,%6,%7}, {%8,%9}, {%0,%1,%2,%3};"
        : "+f"(c[0]), "+f"(c[1]), "+f"(c[2]), "+f"(c[3])
        : "r"(a[0]), "r"(a[1]), "r"(a[2]), "r"(a[3]), "r"(b0), "r"(b1));
}

// ---------------------------------------------------------------------------
// Setup kernels
// ---------------------------------------------------------------------------
__global__ void deg_kernel(const int* __restrict__ dst, int* __restrict__ deg) {
    int e = blockIdx.x * blockDim.x + threadIdx.x;
    if (e < N_EDGES) atomicAdd(&deg[dst[e]], 1);
}

__global__ void scan_kernel(const int* __restrict__ deg,
                            int* __restrict__ row_start,
                            float* __restrict__ invdeg,
                            int* __restrict__ cursor) {
    __shared__ int sm[1024];
    const int t = threadIdx.x;
    const int CH = (N_NODES + 1023) / 1024;
    const int base = t * CH;
    int s = 0;
    for (int i = 0; i < CH; i++) {
        int idx = base + i;
        if (idx < N_NODES) s += deg[idx];
    }
    sm[t] = s;
    __syncthreads();
    for (int d = 1; d < 1024; d <<= 1) {
        int v = (t >= d) ? sm[t - d] : 0;
        __syncthreads();
        sm[t] += v;
        __syncthreads();
    }
    int off = sm[t] - s;
    for (int i = 0; i < CH; i++) {
        int idx = base + i;
        if (idx < N_NODES) {
            row_start[idx] = off;
            int dg = deg[idx];
            off += dg;
            invdeg[idx] = 1.0f / fmaxf((float)dg, 1.0f);
            cursor[idx] = 0;
        }
    }
    if (t == 1023) row_start[N_NODES] = off;
}

// fill: CSR fill (e < N_EDGES) + W fp16 pack (e < 64K) + layer-0 x-half
// prefill (e < N_NODES*64). Grid covers the max.
__global__ void fill_kernel(const int* __restrict__ src,
                            const int* __restrict__ dst,
                            const int* __restrict__ row_start,
                            int* __restrict__ cursor,
                            int* __restrict__ csr_src,
                            const float* __restrict__ Wl,
                            const float* __restrict__ Wr,
                            const float* __restrict__ x,
                            uint32_t* __restrict__ Wh,
                            uint32_t* __restrict__ A) {
    int e = blockIdx.x * blockDim.x + threadIdx.x;
    if (e < N_EDGES) {
        int d = dst[e];
        int p = atomicAdd(&cursor[d], 1);
        csr_src[row_start[d] + p] = src[e];
    }
    if (e < N_LAYERS * D * ROWU32) {
        int k2 = e & (ROWU32 - 1);
        int j  = (e >> 7) & (D - 1);
        int l  = e >> 14;
        int k0 = 2 * k2, k1 = 2 * k2 + 1;
        float w0 = (k0 < D) ? Wl[(l * D + j) * D + k0] : Wr[(l * D + j) * D + (k0 - D)];
        float w1 = (k1 < D) ? Wl[(l * D + j) * D + k1] : Wr[(l * D + j) * D + (k1 - D)];
        Wh[e] = pack_h2(__float2half(w0), __float2half(w1));
    }
    if (e < N_NODES * 64) {                 // layer-0 x-half prefill
        int row = e >> 6;
        int k2l = e & 63;
        float v0 = x[row * D + 2 * k2l];
        float v1 = x[row * D + 2 * k2l + 1];
        A[(size_t)row * ROWU32 + 64 + k2l] = pack_h2(__float2half(v0), __float2half(v1));
    }
}

// ---------------------------------------------------------------------------
// Gather-mean: reads neighbor x-half rows (fp16, 256B/row), accumulates in
// fp32, writes agg-half (fp16). One warp per node; lane owns 4 k-values.
// ---------------------------------------------------------------------------
__global__ __launch_bounds__(256)
void gather_kernel(const uint32_t* __restrict__ A_ro,
                   const int* __restrict__ csr_src,
                   const int* __restrict__ row_start,
                   const float* __restrict__ invdeg,
                   uint32_t* __restrict__ A) {
    int warp = (blockIdx.x * blockDim.x + threadIdx.x) >> 5;
    int lane = threadIdx.x & 31;
    if (warp >= N_NODES) return;
    int b = row_start[warp];
    int e = row_start[warp + 1];
    float4 acc = make_float4(0.f, 0.f, 0.f, 0.f);
    for (int j = b; j < e; j += 32) {
        int cnt = min(32, e - j);
        int sreg = (lane < cnt) ? csr_src[j + lane] : 0;
        for (int i = 0; i < cnt; i++) {
            int si = __shfl_sync(0xffffffffu, sreg, i);
            uint2 v = __ldg((const uint2*)(A_ro + (long long)si * ROWU32 + 64 + 2 * lane));
            float2 f0 = unpack_h2(v.x);
            float2 f1 = unpack_h2(v.y);
            acc.x += f0.x; acc.y += f0.y; acc.z += f1.x; acc.w += f1.y;
        }
    }
    float sc = invdeg[warp];
    acc.x *= sc; acc.y *= sc; acc.z *= sc; acc.w *= sc;
    uint2 o;
    o.x = pack_h2(__float2half(acc.x), __float2half(acc.y));
    o.y = pack_h2(__float2half(acc.z), __float2half(acc.w));
    *(uint2*)(A + (long long)warp * ROWU32 + 2 * lane) = o;
}

// ---------------------------------------------------------------------------
// 1-term fp16 mma.sync GEMM + bias + ReLU — R15 structure, single term.
// CTA 128x128, 8 warps 32x64, K=256 (128 k2) in 8 cp.async double-buffered
// chunks, SAP=20, 2 CTAs/SM. 32 HMMA per warp-chunk.
// Epilogue: last layer -> fp32 out; else -> packed fp16 x-half of A (only
// this CTA's own rows, which it has finished reading).
// ---------------------------------------------------------------------------
#define SAP 20                        // uint32 row stride (16 used)
#define ARR_SZ (128 * SAP)            // 2560 uint32 = 10240 B per operand array
#define BUF_SZ (2 * ARR_SZ)           // A|W
#define GEMM_SMEM (2 * BUF_SZ * 4)    // 40960 B

__global__ __launch_bounds__(256, 2)
void gemm_relu_kernel(uint32_t* __restrict__ A,
                      const uint32_t* __restrict__ Wh,
                      const float* __restrict__ bl,
                      float* __restrict__ out_f32,
                      int last) {
    extern __shared__ uint32_t smem[];
    const uint32_t sbase = smem_u32(smem);
    const int t = threadIdx.x;
    const int lane = t & 31;
    const int w = t >> 5;
    const int wr = (w >> 1) * 32;     // warp row offset
    const int wc = (w & 1) * 64;      // warp col offset
    const int qr = lane >> 2;
    const int qc = lane & 3;
    const int row0 = blockIdx.x * 128;

    float c[2][8][4];
#pragma unroll
    for (int ma = 0; ma < 2; ma++)
#pragma unroll
        for (int na = 0; na < 8; na++)
#pragma unroll
            for (int q = 0; q < 4; q++) c[ma][na][q] = 0.0f;

    auto load_chunk = [&](int i, int b) {
        uint32_t bb = sbase + (uint32_t)(b * BUF_SZ * 4);
#pragma unroll
        for (int s = 0; s < 4; s++) {
            int slot = t + s * 256;       // 0..1023 (2 arrays x 512)
            int arr = slot >> 9;          // 0=A 1=W
            int rem = slot & 511;
            int r = rem >> 2;             // 0..127
            int g = rem & 3;
            uint32_t saddr = bb + (uint32_t)(arr * ARR_SZ * 4 + r * (SAP * 4) + g * 16);
            const uint32_t* gp;
            if (arr == 0) {
                int rg = row0 + r;
                if (rg >= N_NODES) rg = N_NODES - 1;
                gp = A + (long long)rg * ROWU32 + i * 16 + g * 4;
            } else {
                gp = Wh + r * ROWU32 + i * 16 + g * 4;
            }
            cp16(saddr, gp);
        }
        CP_COMMIT();
    };

    load_chunk(0, 0);

    for (int i = 0; i < 8; i++) {
        const int b = i & 1;
        if (i < 7) load_chunk(i + 1, b ^ 1);
        if (i < 7) CP_WAIT(1); else CP_WAIT(0);
        __syncthreads();

        const uint32_t* As = smem + b * BUF_SZ;
        const uint32_t* Ws = As + ARR_SZ;

#pragma unroll
        for (int ks = 0; ks < 2; ks++) {
            const int k2b = ks * 8;
            uint32_t a[2][4];
#pragma unroll
            for (int ma = 0; ma < 2; ma++) {
                int base = (wr + ma * 16 + qr) * SAP + k2b + qc;
                a[ma][0] = As[base];
                a[ma][1] = As[base + 8 * SAP];
                a[ma][2] = As[base + 4];
                a[ma][3] = As[base + 8 * SAP + 4];
            }
#pragma unroll
            for (int na = 0; na < 8; na++) {
                int boff = (wc + na * 8 + qr) * SAP + k2b + qc;
                uint32_t b0 = Ws[boff], b1 = Ws[boff + 4];
                mma_fp16(c[0][na], a[0], b0, b1);
                mma_fp16(c[1][na], a[1], b0, b1);
            }
        }
        __syncthreads();
    }

    // ---- epilogue: bias + relu; last -> fp32 out, else -> fp16 x-half ----
#pragma unroll
    for (int na = 0; na < 8; na++) {
        int col = wc + na * 8 + 2 * qc;    // even column pair (col, col+1)
        float b0 = __ldg(bl + col), b1 = __ldg(bl + col + 1);
        int k2x = 64 + (col >> 1);         // x-half slot for this pair
#pragma unroll
        for (int ma = 0; ma < 2; ma++) {
            int r0 = row0 + wr + ma * 16 + qr;
            int r1 = r0 + 8;
            float ox0 = fmaxf(c[ma][na][0] + b0, 0.f);
            float oy0 = fmaxf(c[ma][na][1] + b1, 0.f);
            float ox1 = fmaxf(c[ma][na][2] + b0, 0.f);
            float oy1 = fmaxf(c[ma][na][3] + b1, 0.f);
            if (r0 < N_NODES) {
                if (last) {
                    *(float2*)(out_f32 + (long long)r0 * D + col) = make_float2(ox0, oy0);
                } else {
                    A[(long long)r0 * ROWU32 + k2x] =
                        pack_h2(__float2half(ox0), __float2half(oy0));
                }
            }
            if (r1 < N_NODES) {
                if (last) {
                    *(float2*)(out_f32 + (long long)r1 * D + col) = make_float2(ox1, oy1);
                } else {
                    A[(long long)r1 * ROWU32 + k2x] =
                        pack_h2(__float2half(ox1), __float2half(oy1));
                }
            }
        }
    }
}

// ---------------------------------------------------------------------------
// kernel_launch
// ---------------------------------------------------------------------------
extern "C" void kernel_launch(void* const* d_in, const int* in_sizes, int n_in,
                              void* d_out, int out_size) {
    const float* x  = (const float*)d_in[0];
    const int*   ei = (const int*)  d_in[1];
    const float* Wl = (const float*)d_in[2];
    const float* bl = (const float*)d_in[3];
    const float* Wr = (const float*)d_in[4];
    float* out = (float*)d_out;

    const int* src = ei;
    const int* dst = ei + N_EDGES;

    float *invdeg;
    int *deg, *cursor, *rowstart, *csr_src;
    uint32_t *A, *wh;
    cudaGetSymbolAddress((void**)&invdeg,   g_invdeg);
    cudaGetSymbolAddress((void**)&deg,      g_deg);
    cudaGetSymbolAddress((void**)&cursor,   g_cursor);
    cudaGetSymbolAddress((void**)&rowstart, g_rowstart);
    cudaGetSymbolAddress((void**)&csr_src,  g_csr_src);
    cudaGetSymbolAddress((void**)&A,        g_A);
    cudaGetSymbolAddress((void**)&wh,       g_Wh);

    cudaFuncSetAttribute(gemm_relu_kernel,
                         cudaFuncAttributeMaxDynamicSharedMemorySize, GEMM_SMEM);

    cudaMemsetAsync(deg, 0, N_NODES * sizeof(int));
    deg_kernel<<<(N_EDGES + 255) / 256, 256>>>(dst, deg);
    scan_kernel<<<1, 1024>>>(deg, rowstart, invdeg, cursor);
    fill_kernel<<<(N_NODES * 64 + 255) / 256, 256>>>(src, dst, rowstart,
                                                     cursor, csr_src,
                                                     Wl, Wr, x, wh, A);

    const int gather_blocks = (N_NODES * 32 + 255) / 256;
    const int gemm_blocks = (N_NODES + 127) / 128;

    for (int l = 0; l < N_LAYERS; l++) {
        gather_kernel<<<gather_blocks, 256>>>(A, csr_src, rowstart, invdeg, A);
        gemm_relu_kernel<<<gemm_blocks, 256, GEMM_SMEM>>>(
            A,
            wh + (size_t)l * D * ROWU32,
            bl + (size_t)l * D,
            out,
            (l == N_LAYERS - 1) ? 1 : 0);
    }
}